// round 4
// baseline (speedup 1.0000x reference)
#include <cuda_runtime.h>
#include <cuda_bf16.h>

#define NB 1024
#define LW 40
#define DIM 128
#define WIN 5
#define NPAIR 370
#define NEG 5
#define NNEG (NPAIR*NEG)      // 1850
#define NSC  (NPAIR + NNEG)   // 2220 scores per walk
#define NROWS (NB*LW)         // 40960 flat walk positions

// bf16 copy of context rows for every flat walk position (indexed by neg_dst_idx directly)
__device__ __nv_bfloat162 g_ctx_bs[NROWS * (DIM / 2)];   // 10.5 MB
__device__ float    g_accum = 0.f;
__device__ unsigned g_count = 0u;

__device__ __forceinline__ float dot4(float4 a, float4 b) {
    return a.x * b.x + a.y * b.y + a.z * b.z + a.w * b.w;
}

// One warp per flat walk row: gather ctx_embed[batch_walk[r]] -> bf16 buffer.
__global__ __launch_bounds__(256) void precompute_kernel(
    const float* __restrict__ ctx_embed,
    const int*   __restrict__ batch_walk)
{
    const int warp = (blockIdx.x * blockDim.x + threadIdx.x) >> 5;
    const int lane = threadIdx.x & 31;
    if (warp >= NROWS) return;
    const int id = __ldg(batch_walk + warp);
    float4 v = *(const float4*)(ctx_embed + (size_t)id * DIM + lane * 4);
    __nv_bfloat162* dst = g_ctx_bs + (size_t)warp * (DIM / 2) + lane * 2;
    dst[0] = __floats2bfloat162_rn(v.x, v.y);
    dst[1] = __floats2bfloat162_rn(v.z, v.w);
}

__global__ __launch_bounds__(256) void walk_kernel(
    const float* __restrict__ node_embed,
    const float* __restrict__ ctx_embed,
    const int*   __restrict__ batch_walk,   // [NB*LW] flat
    const int*   __restrict__ neg_dst_idx,  // [NB*NNEG]
    float*       __restrict__ out)
{
    __shared__ float          node_s[LW * DIM];  // 20480 B
    __shared__ float          ctx_s [LW * DIM];  // 20480 B
    __shared__ int            nid_s [NNEG];      //  7400 B
    __shared__ unsigned short pair_s[NPAIR];     //   740 B
    __shared__ float          wsum  [8];

    const int b   = blockIdx.x;
    const int tid = threadIdx.x;

    // Pair table in reference order (closed-form offsets).
    if (tid < LW) {
        const int i = tid;
        int cum;
        if (i <= 5)       cum = 5 * i + (i * (i - 1)) / 2;
        else if (i <= 35) cum = 35 + 10 * (i - 5);
        else { int m = i - 35; cum = 335 + 9 * m - (m * (m - 1)) / 2; }
        int lo = i - WIN; if (lo < 0) lo = 0;
        int hi = i + 1 + WIN; if (hi > LW) hi = LW;
        for (int j = lo; j < i; j++)     pair_s[cum++] = (unsigned short)(j | (i << 8));
        for (int j = i + 1; j < hi; j++) pair_s[cum++] = (unsigned short)(j | (i << 8));
    }

    // Walk rows into SMEM (fp32, coalesced float4).
    for (int t = tid; t < LW * 32; t += 256) {
        int row = t >> 5, q = t & 31;
        int id = __ldg(batch_walk + b * LW + row);
        size_t base = (size_t)id * DIM + q * 4;
        *(float4*)(node_s + row * DIM + q * 4) = *(const float4*)(node_embed + base);
        *(float4*)(ctx_s  + row * DIM + q * 4) = *(const float4*)(ctx_embed  + base);
    }
    // Negative ctx rows are g_ctx_bs[neg_dst_idx] — single indirection now.
    const int* nd = neg_dst_idx + b * NNEG;
    for (int n = tid; n < NNEG; n += 256) nid_s[n] = nd[n];
    __syncthreads();

    const int warp = tid >> 5, lane = tid & 31;
    const int grp  = lane >> 3, j = lane & 7;     // 4 groups of 8 lanes / warp

    float acc = 0.f;

    for (int q0 = warp * 4; q0 < NSC; q0 += 32) {
        const int q = q0 + grp;
        const bool valid = (q < NSC);

        float partial = 0.f;
        float sign = 1.f;
        if (valid && q < NPAIR) {
            const int pk = pair_s[q];
            const int s = pk & 0xff, d = pk >> 8;
            const float4* A = (const float4*)(node_s + s * DIM);
            const float4* C = (const float4*)(ctx_s  + d * DIM);
            #pragma unroll
            for (int t = 0; t < 4; t++)
                partial += dot4(A[j + 8 * t], C[j + 8 * t]);
            sign = -1.f;
        } else if (valid) {
            const int n = q - NPAIR;
            const int p = n / 5;
            const int d = pair_s[p] >> 8;
            // node side: fp32 SMEM, elements [j*16, j*16+16)
            const float4* A = (const float4*)(node_s + d * DIM) + j * 4;
            // ctx side: bf16 global (L2-resident), 32 B per lane
            const __nv_bfloat162* C = g_ctx_bs + (size_t)nid_s[n] * (DIM / 2) + j * 8;
            uint4 r0 = *(const uint4*)(C);
            uint4 r1 = *(const uint4*)(C + 4);
            const __nv_bfloat162* h0 = (const __nv_bfloat162*)&r0;
            const __nv_bfloat162* h1 = (const __nv_bfloat162*)&r1;
            #pragma unroll
            for (int t = 0; t < 2; t++) {
                float4 a = A[t];
                float2 c0 = __bfloat1622float2(h0[2 * t]);
                float2 c1 = __bfloat1622float2(h0[2 * t + 1]);
                partial += a.x * c0.x + a.y * c0.y + a.z * c1.x + a.w * c1.y;
            }
            #pragma unroll
            for (int t = 0; t < 2; t++) {
                float4 a = A[2 + t];
                float2 c0 = __bfloat1622float2(h1[2 * t]);
                float2 c1 = __bfloat1622float2(h1[2 * t + 1]);
                partial += a.x * c0.x + a.y * c0.y + a.z * c1.x + a.w * c1.y;
            }
        }

        // 3-step butterfly reduces all 4 group-dots at once.
        partial += __shfl_xor_sync(0xffffffffu, partial, 4);
        partial += __shfl_xor_sync(0xffffffffu, partial, 2);
        partial += __shfl_xor_sync(0xffffffffu, partial, 1);

        float x = valid ? sign * fminf(fmaxf(partial, -6.f), 6.f) : -1e30f;
        float sp = __logf(1.f + __expf(x));
        if (j == 0) acc += sp;
    }

    #pragma unroll
    for (int o = 16; o > 0; o >>= 1) acc += __shfl_xor_sync(0xffffffffu, acc, o);
    if (lane == 0) wsum[warp] = acc;
    __syncthreads();

    // Fused global reduction: atomic accumulate, last CTA writes + resets.
    if (tid == 0) {
        float s = 0.f;
        #pragma unroll
        for (int w = 0; w < 8; w++) s += wsum[w];
        atomicAdd(&g_accum, s);
        __threadfence();
        unsigned old = atomicAdd(&g_count, 1u);
        if (old == NB - 1) {
            float total = atomicExch(&g_accum, 0.f);     // read + reset (L2)
            out[0] = total * (1.0f / (float)(NB * NPAIR));
            atomicExch(&g_count, 0u);
        }
    }
}

extern "C" void kernel_launch(void* const* d_in, const int* in_sizes, int n_in,
                              void* d_out, int out_size) {
    const float* node_embed  = (const float*)d_in[0];
    const float* ctx_embed   = (const float*)d_in[1];
    const int*   batch_walk  = (const int*)d_in[2];
    const int*   neg_dst_idx = (const int*)d_in[3];
    float*       out         = (float*)d_out;

    precompute_kernel<<<(NROWS * 32 + 255) / 256, 256>>>(ctx_embed, batch_walk);
    walk_kernel<<<NB, 256>>>(node_embed, ctx_embed, batch_walk, neg_dst_idx, out);
}

// round 6
// speedup vs baseline: 3.0184x; 3.0184x over previous
#include <cuda_runtime.h>
#include <cuda_bf16.h>

#define NB 1024
#define LW 40
#define DIM 128
#define WIN 5
#define NPAIR 370
#define NEG 5
#define NNEG (NPAIR*NEG)      // 1850
#define NROWS (NB*LW)         // 40960 flat walk positions

// bf16 copies of node/context rows for every flat walk position (256 B/row = 16 uint4)
__device__ uint4 g_node_bs[NROWS * 16];   // 10.5 MB
__device__ uint4 g_ctx_bs [NROWS * 16];   // 10.5 MB
__device__ float    g_accum = 0.f;
__device__ unsigned g_count = 0u;

__device__ __forceinline__ float bflo(unsigned u) { return __uint_as_float(u << 16); }
__device__ __forceinline__ float bfhi(unsigned u) { return __uint_as_float(u & 0xffff0000u); }

__device__ __forceinline__ unsigned pack_bf2(float a, float b) {
    __nv_bfloat162 h = __floats2bfloat162_rn(a, b);
    return *reinterpret_cast<unsigned*>(&h);
}

// dot of 8 bf16 dims (one uint4 vs one uint4)
__device__ __forceinline__ float dot_u4(uint4 a, uint4 c) {
    float r;
    r  = bflo(a.x) * bflo(c.x) + bfhi(a.x) * bfhi(c.x);
    r += bflo(a.y) * bflo(c.y) + bfhi(a.y) * bfhi(c.y);
    r += bflo(a.z) * bflo(c.z) + bfhi(a.z) * bfhi(c.z);
    r += bflo(a.w) * bflo(c.w) + bfhi(a.w) * bfhi(c.w);
    return r;
}

// dot of pre-converted f32[8] vs bf16 uint4
__device__ __forceinline__ float dot_fu(const float* f, uint4 c) {
    return f[0] * bflo(c.x) + f[1] * bfhi(c.x) +
           f[2] * bflo(c.y) + f[3] * bfhi(c.y) +
           f[4] * bflo(c.z) + f[5] * bfhi(c.z) +
           f[6] * bflo(c.w) + f[7] * bfhi(c.w);
}

__device__ __forceinline__ void cvt8(uint4 a, float* f) {
    f[0] = bflo(a.x); f[1] = bfhi(a.x);
    f[2] = bflo(a.y); f[3] = bfhi(a.y);
    f[4] = bflo(a.z); f[5] = bfhi(a.z);
    f[6] = bflo(a.w); f[7] = bfhi(a.w);
}

// One warp per flat walk row: gather node/ctx rows -> bf16 tables.
__global__ __launch_bounds__(256) void precompute_kernel(
    const float* __restrict__ node_embed,
    const float* __restrict__ ctx_embed,
    const int*   __restrict__ batch_walk)
{
    const int row  = (blockIdx.x * blockDim.x + threadIdx.x) >> 5;
    const int lane = threadIdx.x & 31;
    if (row >= NROWS) return;
    const int id = __ldg(batch_walk + row);
    float4 vn = *(const float4*)(node_embed + (size_t)id * DIM + lane * 4);
    float4 vc = *(const float4*)(ctx_embed  + (size_t)id * DIM + lane * 4);
    uint2 pn, pc;
    pn.x = pack_bf2(vn.x, vn.y);
    pn.y = pack_bf2(vn.z, vn.w);
    pc.x = pack_bf2(vc.x, vc.y);
    pc.y = pack_bf2(vc.z, vc.w);
    ((uint2*)g_node_bs)[(size_t)row * 32 + lane] = pn;
    ((uint2*)g_ctx_bs )[(size_t)row * 32 + lane] = pc;
}

__global__ __launch_bounds__(256) void walk_kernel(
    const int* __restrict__ neg_dst_idx,  // [NB*NNEG]
    float*     __restrict__ out)
{
    __shared__ uint4          node_sb[LW * 16];  // 10240 B (bf16 rows)
    __shared__ uint4          ctx_sb [LW * 16];  // 10240 B
    __shared__ int            nid_s  [NNEG];     //  7400 B
    __shared__ unsigned short pair_s [NPAIR];    //   740 B
    __shared__ float          wsum   [8];

    const int b   = blockIdx.x;
    const int tid = threadIdx.x;

    // Pair table in reference order (closed-form offsets).
    if (tid < LW) {
        const int i = tid;
        int cum;
        if (i <= 5)       cum = 5 * i + (i * (i - 1)) / 2;
        else if (i <= 35) cum = 35 + 10 * (i - 5);
        else { int m = i - 35; cum = 335 + 9 * m - (m * (m - 1)) / 2; }
        int lo = i - WIN; if (lo < 0) lo = 0;
        int hi = i + 1 + WIN; if (hi > LW) hi = LW;
        for (int j = lo; j < i; j++)     pair_s[cum++] = (unsigned short)(j | (i << 8));
        for (int j = i + 1; j < hi; j++) pair_s[cum++] = (unsigned short)(j | (i << 8));
    }

    // Copy this walk's bf16 rows from the tables (L2-hot, coalesced uint4).
    {
        const uint4* gn = g_node_bs + (size_t)b * LW * 16;
        const uint4* gc = g_ctx_bs  + (size_t)b * LW * 16;
        for (int t = tid; t < LW * 16; t += 256) {
            node_sb[t] = gn[t];
            ctx_sb [t] = gc[t];
        }
    }
    // Negative ctx row indices (single indirection: g_ctx_bs[neg_dst_idx]).
    {
        const int* nd = neg_dst_idx + b * NNEG;
        for (int n = tid; n < NNEG; n += 256) nid_s[n] = nd[n];
    }
    __syncthreads();

    const int warp = tid >> 5, lane = tid & 31;
    const int grp  = lane >> 3, j = lane & 7;   // 4 groups of 8 lanes per warp

    float acc = 0.f;

    // Each 8-lane group handles one PAIR (1 pos + 5 negs) per iteration.
    #pragma unroll 1
    for (int it = 0; it < 12; it++) {
        const int p = it * 32 + warp * 4 + grp;
        const bool valid = (p < NPAIR);
        const int pe = valid ? p : 0;
        const int pk = pair_s[pe];
        const int s = pk & 0xff, d = pk >> 8;

        // Node-dst row: load once, convert once, reuse for all 5 negatives.
        float adf[16];
        cvt8(node_sb[d * 16 + j],     adf);
        cvt8(node_sb[d * 16 + 8 + j], adf + 8);

        float partial[6];
        // Positive: node_src . ctx_dst (both SMEM bf16).
        partial[0] = dot_u4(node_sb[s * 16 + j],     ctx_sb[d * 16 + j]) +
                     dot_u4(node_sb[s * 16 + 8 + j], ctx_sb[d * 16 + 8 + j]);

        // Negatives: 10 independent contiguous LDG.128 (L2-resident bf16 rows).
        uint4 cg0[NEG], cg1[NEG];
        #pragma unroll
        for (int k = 0; k < NEG; k++) {
            const uint4* C = g_ctx_bs + (size_t)nid_s[pe * NEG + k] * 16;
            cg0[k] = C[j];
            cg1[k] = C[j + 8];
        }
        #pragma unroll
        for (int k = 0; k < NEG; k++)
            partial[1 + k] = dot_fu(adf, cg0[k]) + dot_fu(adf + 8, cg1[k]);

        // Reduce all 6 scores across the 8-lane group (3 shfl each).
        #pragma unroll
        for (int k = 0; k < 6; k++) {
            float v = partial[k];
            v += __shfl_xor_sync(0xffffffffu, v, 4);
            v += __shfl_xor_sync(0xffffffffu, v, 2);
            v += __shfl_xor_sync(0xffffffffu, v, 1);
            partial[k] = fminf(fmaxf(v, -6.f), 6.f);
        }

        // Park score j on lane j (pos negated), one softplus for 6 scores.
        float x = -partial[0];
        x = (j == 1) ? partial[1] : x;
        x = (j == 2) ? partial[2] : x;
        x = (j == 3) ? partial[3] : x;
        x = (j == 4) ? partial[4] : x;
        x = (j == 5) ? partial[5] : x;
        if (j >= 6 || !valid) x = -1e30f;
        acc += __logf(1.f + __expf(x));
    }

    // Warp total, CTA total, global atomic.
    #pragma unroll
    for (int o = 16; o > 0; o >>= 1) acc += __shfl_xor_sync(0xffffffffu, acc, o);
    if (lane == 0) wsum[warp] = acc;
    __syncthreads();
    if (tid == 0) {
        float sum = 0.f;
        #pragma unroll
        for (int w = 0; w < 8; w++) sum += wsum[w];
        atomicAdd(&g_accum, sum);
        __threadfence();
        unsigned old = atomicAdd(&g_count, 1u);
        if (old == NB - 1) {
            float total = atomicExch(&g_accum, 0.f);
            out[0] = total * (1.0f / (float)(NB * NPAIR));
            atomicExch(&g_count, 0u);
        }
    }
}

extern "C" void kernel_launch(void* const* d_in, const int* in_sizes, int n_in,
                              void* d_out, int out_size) {
    const float* node_embed  = (const float*)d_in[0];
    const float* ctx_embed   = (const float*)d_in[1];
    const int*   batch_walk  = (const int*)d_in[2];
    const int*   neg_dst_idx = (const int*)d_in[3];
    float*       out         = (float*)d_out;

    precompute_kernel<<<(NROWS * 32 + 255) / 256, 256>>>(node_embed, ctx_embed, batch_walk);
    walk_kernel<<<NB, 256>>>(neg_dst_idx, out);
}

// round 7
// speedup vs baseline: 3.1674x; 1.0494x over previous
#include <cuda_runtime.h>
#include <cuda_bf16.h>

#define NB 1024
#define LW 40
#define DIM 128
#define WIN 5
#define NPAIR 370
#define NEG 5
#define NNEG (NPAIR*NEG)      // 1850
#define NROWS (NB*LW)         // 40960 flat walk positions

// bf16 copies of node/context rows for every flat walk position (256 B/row = 16 uint4)
__device__ uint4 g_node_bs[NROWS * 16];   // 10.5 MB
__device__ uint4 g_ctx_bs [NROWS * 16];   // 10.5 MB
__device__ float    g_accum = 0.f;
__device__ unsigned g_count = 0u;

__device__ __forceinline__ unsigned pack_bf2(float a, float b) {
    __nv_bfloat162 h = __floats2bfloat162_rn(a, b);
    return *reinterpret_cast<unsigned*>(&h);
}

// 8 MACs (8 bf16 dims) in 4 HFMA2 — no decode ALU.
__device__ __forceinline__ __nv_bfloat162 fma8(uint4 a, uint4 c, __nv_bfloat162 acc) {
    const __nv_bfloat162* pa = reinterpret_cast<const __nv_bfloat162*>(&a);
    const __nv_bfloat162* pc = reinterpret_cast<const __nv_bfloat162*>(&c);
    acc = __hfma2(pa[0], pc[0], acc);
    acc = __hfma2(pa[1], pc[1], acc);
    acc = __hfma2(pa[2], pc[2], acc);
    acc = __hfma2(pa[3], pc[3], acc);
    return acc;
}

__device__ __forceinline__ float hsum(__nv_bfloat162 acc) {
    float2 f = __bfloat1622float2(acc);
    return f.x + f.y;
}

// One warp per flat walk row: gather node/ctx rows -> bf16 tables.
__global__ __launch_bounds__(256) void precompute_kernel(
    const float* __restrict__ node_embed,
    const float* __restrict__ ctx_embed,
    const int*   __restrict__ batch_walk)
{
    const int row  = (blockIdx.x * blockDim.x + threadIdx.x) >> 5;
    const int lane = threadIdx.x & 31;
    if (row >= NROWS) return;
    const int id = __ldg(batch_walk + row);
    float4 vn = *(const float4*)(node_embed + (size_t)id * DIM + lane * 4);
    float4 vc = *(const float4*)(ctx_embed  + (size_t)id * DIM + lane * 4);
    uint2 pn, pc;
    pn.x = pack_bf2(vn.x, vn.y);
    pn.y = pack_bf2(vn.z, vn.w);
    pc.x = pack_bf2(vc.x, vc.y);
    pc.y = pack_bf2(vc.z, vc.w);
    ((uint2*)g_node_bs)[(size_t)row * 32 + lane] = pn;
    ((uint2*)g_ctx_bs )[(size_t)row * 32 + lane] = pc;
}

__global__ __launch_bounds__(256) void walk_kernel(
    const int* __restrict__ neg_dst_idx,  // [NB*NNEG]
    float*     __restrict__ out)
{
    __shared__ uint4          node_sb[LW * 16];  // 10240 B (bf16 rows)
    __shared__ uint4          ctx_sb [LW * 16];  // 10240 B
    __shared__ int            nid_s  [NNEG];     //  7400 B
    __shared__ unsigned short pair_s [NPAIR];    //   740 B
    __shared__ float          wsum   [8];

    const int b   = blockIdx.x;
    const int tid = threadIdx.x;

    // Pair table in reference order (closed-form offsets).
    if (tid < LW) {
        const int i = tid;
        int cum;
        if (i <= 5)       cum = 5 * i + (i * (i - 1)) / 2;
        else if (i <= 35) cum = 35 + 10 * (i - 5);
        else { int m = i - 35; cum = 335 + 9 * m - (m * (m - 1)) / 2; }
        int lo = i - WIN; if (lo < 0) lo = 0;
        int hi = i + 1 + WIN; if (hi > LW) hi = LW;
        for (int j = lo; j < i; j++)     pair_s[cum++] = (unsigned short)(j | (i << 8));
        for (int j = i + 1; j < hi; j++) pair_s[cum++] = (unsigned short)(j | (i << 8));
    }

    // Copy this walk's bf16 rows from the tables (L2-hot, coalesced uint4).
    {
        const uint4* gn = g_node_bs + (size_t)b * LW * 16;
        const uint4* gc = g_ctx_bs  + (size_t)b * LW * 16;
        for (int t = tid; t < LW * 16; t += 256) {
            node_sb[t] = gn[t];
            ctx_sb [t] = gc[t];
        }
    }
    // Negative ctx row indices (single indirection: g_ctx_bs[neg_dst_idx]).
    {
        const int* nd = neg_dst_idx + b * NNEG;
        for (int n = tid; n < NNEG; n += 256) nid_s[n] = nd[n];
    }
    __syncthreads();

    const int warp = tid >> 5, lane = tid & 31;
    const int grp  = lane >> 3, j = lane & 7;   // 4 groups of 8 lanes per warp

    const __nv_bfloat162 zero2 = __floats2bfloat162_rn(0.f, 0.f);
    float acc = 0.f;

    // Each 8-lane group handles one PAIR (1 pos + 5 negs) per iteration.
    #pragma unroll 1
    for (int it = 0; it < 12; it++) {
        const int p = it * 32 + warp * 4 + grp;
        const bool valid = (p < NPAIR);
        const int pe = valid ? p : 0;
        const int pk = pair_s[pe];
        const int s = pk & 0xff, d = pk >> 8;

        // Node rows (bf16x2 registers, reused across the 5 negatives).
        const uint4 ad0 = node_sb[d * 16 + j];
        const uint4 ad1 = node_sb[d * 16 + 8 + j];

        float partial[6];
        // Positive: node_src . ctx_dst (both SMEM bf16).
        {
            __nv_bfloat162 h = zero2;
            h = fma8(node_sb[s * 16 + j],     ctx_sb[d * 16 + j],     h);
            h = fma8(node_sb[s * 16 + 8 + j], ctx_sb[d * 16 + 8 + j], h);
            partial[0] = hsum(h);
        }

        // Negatives: 10 independent contiguous LDG.128 (L2-resident bf16 rows).
        uint4 cg0[NEG], cg1[NEG];
        #pragma unroll
        for (int k = 0; k < NEG; k++) {
            const uint4* C = g_ctx_bs + (size_t)nid_s[pe * NEG + k] * 16;
            cg0[k] = C[j];
            cg1[k] = C[j + 8];
        }
        #pragma unroll
        for (int k = 0; k < NEG; k++) {
            __nv_bfloat162 h = zero2;
            h = fma8(ad0, cg0[k], h);
            h = fma8(ad1, cg1[k], h);
            partial[1 + k] = hsum(h);
        }

        // Reduce all 6 scores across the 8-lane group (3 shfl each).
        #pragma unroll
        for (int k = 0; k < 6; k++) {
            float v = partial[k];
            v += __shfl_xor_sync(0xffffffffu, v, 4);
            v += __shfl_xor_sync(0xffffffffu, v, 2);
            v += __shfl_xor_sync(0xffffffffu, v, 1);
            partial[k] = fminf(fmaxf(v, -6.f), 6.f);
        }

        // Park score j on lane j (pos negated), one softplus for 6 scores.
        float x = -partial[0];
        x = (j == 1) ? partial[1] : x;
        x = (j == 2) ? partial[2] : x;
        x = (j == 3) ? partial[3] : x;
        x = (j == 4) ? partial[4] : x;
        x = (j == 5) ? partial[5] : x;
        if (j >= 6 || !valid) x = -1e30f;
        acc += __logf(1.f + __expf(x));
    }

    // Warp total, CTA total, global atomic.
    #pragma unroll
    for (int o = 16; o > 0; o >>= 1) acc += __shfl_xor_sync(0xffffffffu, acc, o);
    if (lane == 0) wsum[warp] = acc;
    __syncthreads();
    if (tid == 0) {
        float sum = 0.f;
        #pragma unroll
        for (int w = 0; w < 8; w++) sum += wsum[w];
        atomicAdd(&g_accum, sum);
        __threadfence();
        unsigned old = atomicAdd(&g_count, 1u);
        if (old == NB - 1) {
            float total = atomicExch(&g_accum, 0.f);
            out[0] = total * (1.0f / (float)(NB * NPAIR));
            atomicExch(&g_count, 0u);
        }
    }
}

extern "C" void kernel_launch(void* const* d_in, const int* in_sizes, int n_in,
                              void* d_out, int out_size) {
    const float* node_embed  = (const float*)d_in[0];
    const float* ctx_embed   = (const float*)d_in[1];
    const int*   batch_walk  = (const int*)d_in[2];
    const int*   neg_dst_idx = (const int*)d_in[3];
    float*       out         = (float*)d_out;

    precompute_kernel<<<(NROWS * 32 + 255) / 256, 256>>>(node_embed, ctx_embed, batch_walk);
    walk_kernel<<<NB, 256>>>(neg_dst_idx, out);
}

// round 8
// speedup vs baseline: 3.5191x; 1.1110x over previous
#include <cuda_runtime.h>
#include <cuda_bf16.h>

#define NB 1024
#define LW 40
#define DIM 128
#define WIN 5
#define NPAIR 370
#define NEG 5
#define NNEG (NPAIR*NEG)      // 1850
#define NROWS (NB*LW)         // 40960 flat walk positions

// int8-quantized copies of node/context rows (128 B/row = 8 uint4) + per-row scales.
__device__ uint4 g_node_i8[NROWS * 8];     // 5.24 MB
__device__ uint4 g_ctx_i8 [NROWS * 8];     // 5.24 MB
__device__ float g_node_sc[NROWS];
__device__ float g_ctx_sc [NROWS];
__device__ float    g_accum = 0.f;
__device__ unsigned g_count = 0u;

__device__ __forceinline__ int dp16(uint4 a, uint4 b, int acc) {
    acc = __dp4a((int)a.x, (int)b.x, acc);
    acc = __dp4a((int)a.y, (int)b.y, acc);
    acc = __dp4a((int)a.z, (int)b.z, acc);
    acc = __dp4a((int)a.w, (int)b.w, acc);
    return acc;
}

__device__ __forceinline__ unsigned pack4(float4 v, float rs) {
    int q0 = __float2int_rn(v.x * rs);
    int q1 = __float2int_rn(v.y * rs);
    int q2 = __float2int_rn(v.z * rs);
    int q3 = __float2int_rn(v.w * rs);
    return (q0 & 0xff) | ((q1 & 0xff) << 8) | ((q2 & 0xff) << 16) | (q3 << 24);
}

// One warp per flat walk row: amax -> int8 quantize node+ctx rows.
__global__ __launch_bounds__(256) void precompute_kernel(
    const float* __restrict__ node_embed,
    const float* __restrict__ ctx_embed,
    const int*   __restrict__ batch_walk)
{
    const int row  = (blockIdx.x * blockDim.x + threadIdx.x) >> 5;
    const int lane = threadIdx.x & 31;
    if (row >= NROWS) return;
    const int id = __ldg(batch_walk + row);
    float4 vn = *(const float4*)(node_embed + (size_t)id * DIM + lane * 4);
    float4 vc = *(const float4*)(ctx_embed  + (size_t)id * DIM + lane * 4);

    float an = fmaxf(fmaxf(fabsf(vn.x), fabsf(vn.y)), fmaxf(fabsf(vn.z), fabsf(vn.w)));
    float ac = fmaxf(fmaxf(fabsf(vc.x), fabsf(vc.y)), fmaxf(fabsf(vc.z), fabsf(vc.w)));
    #pragma unroll
    for (int o = 16; o > 0; o >>= 1) {
        an = fmaxf(an, __shfl_xor_sync(0xffffffffu, an, o));
        ac = fmaxf(ac, __shfl_xor_sync(0xffffffffu, ac, o));
    }
    an = fmaxf(an, 1e-30f);
    ac = fmaxf(ac, 1e-30f);
    const float rsn = 127.f / an, rsc = 127.f / ac;

    ((unsigned*)g_node_i8)[(size_t)row * 32 + lane] = pack4(vn, rsn);
    ((unsigned*)g_ctx_i8 )[(size_t)row * 32 + lane] = pack4(vc, rsc);
    if (lane == 0) {
        g_node_sc[row] = an * (1.f / 127.f);
        g_ctx_sc [row] = ac * (1.f / 127.f);
    }
}

__global__ __launch_bounds__(256) void walk_kernel(
    const int* __restrict__ neg_dst_idx,  // [NB*NNEG]
    float*     __restrict__ out)
{
    __shared__ uint4          node_s8[LW * 8];   // 5120 B (int8 rows)
    __shared__ uint4          ctx_s8 [LW * 8];   // 5120 B
    __shared__ float          nsc_s  [LW];
    __shared__ float          csc_s  [LW];
    __shared__ int            nid_s  [NNEG];     // 7400 B
    __shared__ unsigned short pair_s [NPAIR];    //  740 B
    __shared__ float          wsum   [8];        // ~18.8 KB total

    const int b   = blockIdx.x;
    const int tid = threadIdx.x;

    // Pair table in reference order (closed-form offsets).
    if (tid < LW) {
        const int i = tid;
        int cum;
        if (i <= 5)       cum = 5 * i + (i * (i - 1)) / 2;
        else if (i <= 35) cum = 35 + 10 * (i - 5);
        else { int m = i - 35; cum = 335 + 9 * m - (m * (m - 1)) / 2; }
        int lo = i - WIN; if (lo < 0) lo = 0;
        int hi = i + 1 + WIN; if (hi > LW) hi = LW;
        for (int j = lo; j < i; j++)     pair_s[cum++] = (unsigned short)(j | (i << 8));
        for (int j = i + 1; j < hi; j++) pair_s[cum++] = (unsigned short)(j | (i << 8));
        nsc_s[tid] = g_node_sc[b * LW + tid];
        csc_s[tid] = g_ctx_sc [b * LW + tid];
    }

    // Copy this walk's int8 rows into SMEM (L2-hot, coalesced uint4).
    {
        const uint4* gn = g_node_i8 + (size_t)b * LW * 8;
        const uint4* gc = g_ctx_i8  + (size_t)b * LW * 8;
        for (int t = tid; t < LW * 8; t += 256) {
            node_s8[t] = gn[t];
            ctx_s8 [t] = gc[t];
        }
    }
    // Negative ctx row indices.
    {
        const int* nd = neg_dst_idx + b * NNEG;
        for (int n = tid; n < NNEG; n += 256) nid_s[n] = nd[n];
    }
    __syncthreads();

    const int warp = tid >> 5, lane = tid & 31;
    const int grp  = lane >> 3, j = lane & 7;   // 4 groups of 8 lanes per warp

    float acc = 0.f;

    // Each 8-lane group handles one PAIR (1 pos + 5 negs) per iteration.
    #pragma unroll 1
    for (int it = 0; it < 12; it++) {
        const int p = it * 32 + warp * 4 + grp;
        const bool valid = (p < NPAIR);
        const int pe = valid ? p : 0;
        const int pk = pair_s[pe];
        const int s = pk & 0xff, d = pk >> 8;

        // Rows: 1 LDS.128 each (lane j takes uint4 j of the 128-B row).
        const uint4 qs = node_s8[s * 8 + j];    // node_src
        const uint4 qd = node_s8[d * 8 + j];    // node_dst (reused x5)
        const uint4 qc = ctx_s8 [d * 8 + j];    // ctx_dst

        int ip[6];
        ip[0] = dp16(qs, qc, 0);                // positive

        // 5 negatives: 1 LDG.128 per row (L2-resident int8 rows).
        uint4 cg[NEG];
        #pragma unroll
        for (int k = 0; k < NEG; k++)
            cg[k] = g_ctx_i8[(size_t)nid_s[pe * NEG + k] * 8 + j];
        #pragma unroll
        for (int k = 0; k < NEG; k++)
            ip[1 + k] = dp16(qd, cg[k], 0);

        // Reduce 6 int scores across the 8-lane group (exact).
        #pragma unroll
        for (int k = 0; k < 6; k++) {
            int v = ip[k];
            v += __shfl_xor_sync(0xffffffffu, v, 4);
            v += __shfl_xor_sync(0xffffffffu, v, 2);
            v += __shfl_xor_sync(0xffffffffu, v, 1);
            ip[k] = v;
        }

        // Park score j on lane j; apply per-row scales; one softplus / 6 scores.
        int iv = ip[0];
        iv = (j == 1) ? ip[1] : iv;
        iv = (j == 2) ? ip[2] : iv;
        iv = (j == 3) ? ip[3] : iv;
        iv = (j == 4) ? ip[4] : iv;
        iv = (j == 5) ? ip[5] : iv;

        float sA = (j == 0) ? nsc_s[s] : nsc_s[d];
        float sB;
        if (j == 0)      sB = csc_s[d];
        else if (j <= 5) sB = __ldg(g_ctx_sc + nid_s[pe * NEG + (j - 1)]);
        else             sB = 0.f;

        float x = (float)iv * sA * sB;
        x = fminf(fmaxf(x, -6.f), 6.f);
        if (j == 0) x = -x;                       // pos: softplus(-v)
        if (j >= 6 || !valid) x = -1e30f;
        acc += __logf(1.f + __expf(x));
    }

    // Warp total, CTA total, global atomic.
    #pragma unroll
    for (int o = 16; o > 0; o >>= 1) acc += __shfl_xor_sync(0xffffffffu, acc, o);
    if (lane == 0) wsum[warp] = acc;
    __syncthreads();
    if (tid == 0) {
        float sum = 0.f;
        #pragma unroll
        for (int w = 0; w < 8; w++) sum += wsum[w];
        atomicAdd(&g_accum, sum);
        __threadfence();
        unsigned old = atomicAdd(&g_count, 1u);
        if (old == NB - 1) {
            float total = atomicExch(&g_accum, 0.f);
            out[0] = total * (1.0f / (float)(NB * NPAIR));
            atomicExch(&g_count, 0u);
        }
    }
}

extern "C" void kernel_launch(void* const* d_in, const int* in_sizes, int n_in,
                              void* d_out, int out_size) {
    const float* node_embed  = (const float*)d_in[0];
    const float* ctx_embed   = (const float*)d_in[1];
    const int*   batch_walk  = (const int*)d_in[2];
    const int*   neg_dst_idx = (const int*)d_in[3];
    float*       out         = (float*)d_out;

    precompute_kernel<<<(NROWS * 32 + 255) / 256, 256>>>(node_embed, ctx_embed, batch_walk);
    walk_kernel<<<NB, 256>>>(neg_dst_idx, out);
}

// round 9
// speedup vs baseline: 3.5356x; 1.0047x over previous
#include <cuda_runtime.h>
#include <cuda_bf16.h>

#define NB 1024
#define LW 40
#define DIM 128
#define WIN 5
#define NPAIR 370
#define NEG 5
#define NNEG (NPAIR*NEG)      // 1850
#define NROWS (NB*LW)         // 40960 flat walk positions

// int8-quantized copies of node/context rows (128 B/row = 8 uint4).
__device__ uint4 g_node_i8[NROWS * 8];     // 5.24 MB
__device__ uint4 g_ctx_i8 [NROWS * 8];     // 5.24 MB
__device__ float g_node_sc[NROWS];         // per-row node scale (amax/127)
__device__ float g_ctx_sc [NROWS];         // per-row ctx amax (K1 output)
__device__ float g_gsc    = 0.f;           // global ctx scale (amax/127)
__device__ float    g_accum = 0.f;
__device__ unsigned g_count = 0u;

__device__ __forceinline__ int dp16(uint4 a, uint4 b, int acc) {
    acc = __dp4a((int)a.x, (int)b.x, acc);
    acc = __dp4a((int)a.y, (int)b.y, acc);
    acc = __dp4a((int)a.z, (int)b.z, acc);
    acc = __dp4a((int)a.w, (int)b.w, acc);
    return acc;
}

__device__ __forceinline__ unsigned pack4(float4 v, float rs) {
    int q0 = __float2int_rn(v.x * rs);
    int q1 = __float2int_rn(v.y * rs);
    int q2 = __float2int_rn(v.z * rs);
    int q3 = __float2int_rn(v.w * rs);
    return (q0 & 0xff) | ((q1 & 0xff) << 8) | ((q2 & 0xff) << 16) | (q3 << 24);
}

// K1: one warp per flat walk row. Node rows: quantize per-row. Ctx rows: amax only.
__global__ __launch_bounds__(256) void precompute_kernel(
    const float* __restrict__ node_embed,
    const float* __restrict__ ctx_embed,
    const int*   __restrict__ batch_walk)
{
    const int row  = (blockIdx.x * blockDim.x + threadIdx.x) >> 5;
    const int lane = threadIdx.x & 31;
    if (row >= NROWS) return;
    const int id = __ldg(batch_walk + row);
    float4 vn = *(const float4*)(node_embed + (size_t)id * DIM + lane * 4);
    float4 vc = *(const float4*)(ctx_embed  + (size_t)id * DIM + lane * 4);

    float an = fmaxf(fmaxf(fabsf(vn.x), fabsf(vn.y)), fmaxf(fabsf(vn.z), fabsf(vn.w)));
    float ac = fmaxf(fmaxf(fabsf(vc.x), fabsf(vc.y)), fmaxf(fabsf(vc.z), fabsf(vc.w)));
    #pragma unroll
    for (int o = 16; o > 0; o >>= 1) {
        an = fmaxf(an, __shfl_xor_sync(0xffffffffu, an, o));
        ac = fmaxf(ac, __shfl_xor_sync(0xffffffffu, ac, o));
    }
    an = fmaxf(an, 1e-30f);
    ac = fmaxf(ac, 1e-30f);

    ((unsigned*)g_node_i8)[(size_t)row * 32 + lane] = pack4(vn, 127.f / an);
    if (lane == 0) {
        g_node_sc[row] = an * (1.f / 127.f);
        g_ctx_sc [row] = ac;                    // raw amax for K2
    }
}

// K2: single CTA reduces global ctx amax -> g_gsc.
__global__ __launch_bounds__(1024) void reduce_scale_kernel() {
    __shared__ float sm[1024];
    float m = 0.f;
    for (int i = threadIdx.x; i < NROWS; i += 1024) m = fmaxf(m, g_ctx_sc[i]);
    sm[threadIdx.x] = m;
    __syncthreads();
    for (int s = 512; s > 0; s >>= 1) {
        if (threadIdx.x < s) sm[threadIdx.x] = fmaxf(sm[threadIdx.x], sm[threadIdx.x + s]);
        __syncthreads();
    }
    if (threadIdx.x == 0) g_gsc = fmaxf(sm[0], 1e-30f) * (1.f / 127.f);
}

// K3: quantize ctx rows with the global scale (ctx_embed rows are L2-hot from K1).
__global__ __launch_bounds__(256) void quant_ctx_kernel(
    const float* __restrict__ ctx_embed,
    const int*   __restrict__ batch_walk)
{
    const int row  = (blockIdx.x * blockDim.x + threadIdx.x) >> 5;
    const int lane = threadIdx.x & 31;
    if (row >= NROWS) return;
    const float rs = 1.f / g_gsc;               // = 127 / global_amax
    const int id = __ldg(batch_walk + row);
    float4 vc = *(const float4*)(ctx_embed + (size_t)id * DIM + lane * 4);
    ((unsigned*)g_ctx_i8)[(size_t)row * 32 + lane] = pack4(vc, rs);
}

__global__ __launch_bounds__(256) void walk_kernel(
    const int* __restrict__ neg_dst_idx,  // [NB*NNEG]
    float*     __restrict__ out)
{
    __shared__ uint4          node_s8[LW * 8];   // 5120 B (int8 rows)
    __shared__ uint4          ctx_s8 [LW * 8];   // 5120 B
    __shared__ float          nsc2_s [LW];       // node_row_scale * g_gsc
    __shared__ int            nid_s  [NNEG];     // 7400 B
    __shared__ unsigned short pair_s [NPAIR];    //  740 B
    __shared__ float          wsum   [8];

    const int b   = blockIdx.x;
    const int tid = threadIdx.x;

    // Pair table in reference order (closed-form offsets).
    if (tid < LW) {
        const int i = tid;
        int cum;
        if (i <= 5)       cum = 5 * i + (i * (i - 1)) / 2;
        else if (i <= 35) cum = 35 + 10 * (i - 5);
        else { int m = i - 35; cum = 335 + 9 * m - (m * (m - 1)) / 2; }
        int lo = i - WIN; if (lo < 0) lo = 0;
        int hi = i + 1 + WIN; if (hi > LW) hi = LW;
        for (int j = lo; j < i; j++)     pair_s[cum++] = (unsigned short)(j | (i << 8));
        for (int j = i + 1; j < hi; j++) pair_s[cum++] = (unsigned short)(j | (i << 8));
        nsc2_s[tid] = g_node_sc[b * LW + tid] * g_gsc;
    }

    // Copy this walk's int8 rows into SMEM (L2-hot, coalesced uint4).
    {
        const uint4* gn = g_node_i8 + (size_t)b * LW * 8;
        const uint4* gc = g_ctx_i8  + (size_t)b * LW * 8;
        for (int t = tid; t < LW * 8; t += 256) {
            node_s8[t] = gn[t];
            ctx_s8 [t] = gc[t];
        }
    }
    // Negative ctx row indices.
    {
        const int* nd = neg_dst_idx + b * NNEG;
        for (int n = tid; n < NNEG; n += 256) nid_s[n] = nd[n];
    }
    __syncthreads();

    const int warp = tid >> 5, lane = tid & 31;
    const int grp  = lane >> 3, j = lane & 7;   // 4 groups of 8 lanes per warp

    float acc = 0.f;

    // Each 8-lane group handles one PAIR (1 pos + 5 negs) per iteration.
    #pragma unroll 1
    for (int it = 0; it < 12; it++) {
        const int p = it * 32 + warp * 4 + grp;
        const bool valid = (p < NPAIR);
        const int pe = valid ? p : 0;
        const int pk = pair_s[pe];
        const int s = pk & 0xff, d = pk >> 8;

        // Rows: 1 LDS.128 each (lane j takes uint4 j of the 128-B row).
        const uint4 qs = node_s8[s * 8 + j];    // node_src
        const uint4 qd = node_s8[d * 8 + j];    // node_dst (reused x5)
        const uint4 qc = ctx_s8 [d * 8 + j];    // ctx_dst

        int ip[6];
        ip[0] = dp16(qs, qc, 0);                // positive

        // 5 negatives: 1 LDG.128 per row (L2-resident int8 rows).
        uint4 cg[NEG];
        #pragma unroll
        for (int k = 0; k < NEG; k++)
            cg[k] = g_ctx_i8[(size_t)nid_s[pe * NEG + k] * 8 + j];
        #pragma unroll
        for (int k = 0; k < NEG; k++)
            ip[1 + k] = dp16(qd, cg[k], 0);

        // Reduce 6 int scores across the 8-lane group (exact).
        #pragma unroll
        for (int k = 0; k < 6; k++) {
            int v = ip[k];
            v += __shfl_xor_sync(0xffffffffu, v, 4);
            v += __shfl_xor_sync(0xffffffffu, v, 2);
            v += __shfl_xor_sync(0xffffffffu, v, 1);
            ip[k] = v;
        }

        // Park score j on lane j; scale = node_row_scale * global_ctx_scale.
        int iv = ip[0];
        iv = (j == 1) ? ip[1] : iv;
        iv = (j == 2) ? ip[2] : iv;
        iv = (j == 3) ? ip[3] : iv;
        iv = (j == 4) ? ip[4] : iv;
        iv = (j == 5) ? ip[5] : iv;

        float x = (float)iv * nsc2_s[(j == 0) ? s : d];
        x = fminf(fmaxf(x, -6.f), 6.f);
        if (j == 0) x = -x;                       // pos: softplus(-v)
        if (j >= 6 || !valid) x = -1e30f;
        acc += __logf(1.f + __expf(x));
    }

    // Warp total, CTA total, global atomic.
    #pragma unroll
    for (int o = 16; o > 0; o >>= 1) acc += __shfl_xor_sync(0xffffffffu, acc, o);
    if (lane == 0) wsum[warp] = acc;
    __syncthreads();
    if (tid == 0) {
        float sum = 0.f;
        #pragma unroll
        for (int w = 0; w < 8; w++) sum += wsum[w];
        atomicAdd(&g_accum, sum);
        __threadfence();
        unsigned old = atomicAdd(&g_count, 1u);
        if (old == NB - 1) {
            float total = atomicExch(&g_accum, 0.f);
            out[0] = total * (1.0f / (float)(NB * NPAIR));
            atomicExch(&g_count, 0u);
        }
    }
}

extern "C" void kernel_launch(void* const* d_in, const int* in_sizes, int n_in,
                              void* d_out, int out_size) {
    const float* node_embed  = (const float*)d_in[0];
    const float* ctx_embed   = (const float*)d_in[1];
    const int*   batch_walk  = (const int*)d_in[2];
    const int*   neg_dst_idx = (const int*)d_in[3];
    float*       out         = (float*)d_out;

    precompute_kernel<<<(NROWS * 32 + 255) / 256, 256>>>(node_embed, ctx_embed, batch_walk);
    reduce_scale_kernel<<<1, 1024>>>();
    quant_ctx_kernel<<<(NROWS * 32 + 255) / 256, 256>>>(ctx_embed, batch_walk);
    walk_kernel<<<NB, 256>>>(neg_dst_idx, out);
}